// round 1
// baseline (speedup 1.0000x reference)
#include <cuda_runtime.h>
#include <cuda_bf16.h>
#include <math.h>

// ---------------------------------------------------------------------------
// Problem dims (fixed by the reference)
// ---------------------------------------------------------------------------
#define BSZ 4
#define LQ  2048
#define SK  1024
#define DM  1024
#define DL  4096
#define NH  16
#define DHEAD 64

// ---------------------------------------------------------------------------
// Scratch (device globals; no runtime allocation allowed)
// ---------------------------------------------------------------------------
__device__ float g_Q[(size_t)BSZ * LQ * DM];   // 32 MB  [B*L, 1024]
__device__ float g_K[(size_t)BSZ * SK * DM];   // 16 MB  [B*S, 1024]
__device__ float g_V[(size_t)BSZ * SK * DM];   // 16 MB
__device__ float g_A[(size_t)BSZ * LQ * DM];   // 32 MB  attention output

// ---------------------------------------------------------------------------
// SGEMM + bias: C[M,N] = A[M,K] @ W[K,N] + bias[N]
// 128x128 block tile, BK=16, 256 threads, 8x8 microtile.
// M % 128 == 0, N % 128 == 0, K % 16 == 0 (true for all four calls).
// ---------------------------------------------------------------------------
#define GBM 128
#define GBN 128
#define GBK 16
#define AS_STRIDE (GBM + 4)   // 132 words: keeps float4 alignment, spreads banks

__global__ __launch_bounds__(256, 2) void sgemm_bias(
    const float* __restrict__ A, const float* __restrict__ W,
    const float* __restrict__ bias, float* __restrict__ C,
    int M, int N, int K)
{
    __shared__ float As[GBK * AS_STRIDE];  // transposed A tile: As[k][m]
    __shared__ float Bs[GBK * GBN];        // Bs[k][n]

    const int tid = threadIdx.x;
    const int tx = tid & 15;   // 16 col groups * 8 = 128
    const int ty = tid >> 4;   // 16 row groups * 8 = 128
    const int bx = blockIdx.x; // N tile
    const int by = blockIdx.y; // M tile

    const float* Ablk = A + (size_t)by * GBM * K;
    const float* Wblk = W + (size_t)bx * GBN;

    float acc[8][8];
#pragma unroll
    for (int i = 0; i < 8; i++)
#pragma unroll
        for (int j = 0; j < 8; j++) acc[i][j] = 0.f;

    for (int k0 = 0; k0 < K; k0 += GBK) {
        // --- load A tile (128x16) transposed, B tile (16x128) ---
#pragma unroll
        for (int it = 0; it < 2; it++) {
            int v = tid + 256 * it;          // 0..511 float4 slots
            int ar = v >> 2;                 // 0..127
            int ac = (v & 3) * 4;            // 0,4,8,12
            float4 a4 = *(const float4*)(Ablk + (size_t)ar * K + k0 + ac);
            As[(ac + 0) * AS_STRIDE + ar] = a4.x;
            As[(ac + 1) * AS_STRIDE + ar] = a4.y;
            As[(ac + 2) * AS_STRIDE + ar] = a4.z;
            As[(ac + 3) * AS_STRIDE + ar] = a4.w;
            int br = v >> 5;                 // 0..15
            int bc = (v & 31) * 4;           // 0..124
            float4 b4 = *(const float4*)(Wblk + (size_t)(k0 + br) * N + bc);
            *(float4*)&Bs[br * GBN + bc] = b4;
        }
        __syncthreads();

#pragma unroll
        for (int k = 0; k < GBK; k++) {
            float a[8], b[8];
            *(float4*)&a[0] = *(const float4*)&As[k * AS_STRIDE + ty * 8];
            *(float4*)&a[4] = *(const float4*)&As[k * AS_STRIDE + ty * 8 + 4];
            *(float4*)&b[0] = *(const float4*)&Bs[k * GBN + tx * 8];
            *(float4*)&b[4] = *(const float4*)&Bs[k * GBN + tx * 8 + 4];
#pragma unroll
            for (int i = 0; i < 8; i++)
#pragma unroll
                for (int j = 0; j < 8; j++) acc[i][j] += a[i] * b[j];
        }
        __syncthreads();
    }

    // --- epilogue: add bias, store ---
    float bv[8];
#pragma unroll
    for (int j = 0; j < 8; j++) bv[j] = bias[bx * GBN + tx * 8 + j];
#pragma unroll
    for (int i = 0; i < 8; i++) {
        size_t r = (size_t)by * GBM + ty * 8 + i;
        int c = bx * GBN + tx * 8;
        float4 o0, o1;
        o0.x = acc[i][0] + bv[0]; o0.y = acc[i][1] + bv[1];
        o0.z = acc[i][2] + bv[2]; o0.w = acc[i][3] + bv[3];
        o1.x = acc[i][4] + bv[4]; o1.y = acc[i][5] + bv[5];
        o1.z = acc[i][6] + bv[6]; o1.w = acc[i][7] + bv[7];
        *(float4*)(C + r * N + c)     = o0;
        *(float4*)(C + r * N + c + 4) = o1;
    }
}

// ---------------------------------------------------------------------------
// Flash-style attention.
// Per block: one (batch b, head h), 128 query rows. Loops over S in 64-key
// tiles with online softmax. 256 threads as 16(ty) x 16(tx), microtile
// 8 rows x 4 cols. Dynamic smem ~100 KB.
//   Q/K/V are [B*rows, 1024] with head h at cols h*64..h*64+63.
// ---------------------------------------------------------------------------
#define AT_BM 128
#define AT_BN 64
#define AT_STR 65   // smem row stride (words)

__global__ __launch_bounds__(256, 2) void attn_kernel(
    const float* __restrict__ Q, const float* __restrict__ K,
    const float* __restrict__ V, float* __restrict__ Aout)
{
    extern __shared__ float sm[];
    float* Qs = sm;                       // [128][65]
    float* Ks = Qs + AT_BM * AT_STR;      // [64][65]
    float* Vs = Ks + AT_BN * AT_STR;      // [64][65]
    float* Ps = Vs + AT_BN * AT_STR;      // [128][65]

    const int tid = threadIdx.x;
    const int tx = tid & 15;   // score col group (4 each)
    const int ty = tid >> 4;   // row group (8 each)
    const int mt = blockIdx.x; // query tile: 0..15
    const int h  = blockIdx.y;
    const int b  = blockIdx.z;
    const int l0 = mt * AT_BM;
    const float scale = 0.125f;  // 1/sqrt(64)

    const float* Qg = Q + ((size_t)(b * LQ + l0)) * DM + h * DHEAD;
    const float* Kg = K + ((size_t)(b * SK)) * DM + h * DHEAD;
    const float* Vg = V + ((size_t)(b * SK)) * DM + h * DHEAD;

    // load Q tile 128x64
#pragma unroll
    for (int it = 0; it < 8; it++) {
        int v = tid + 256 * it;       // 0..2047 float4 slots
        int r = v >> 4;               // 0..127
        int c = (v & 15) * 4;         // 0..60
        float4 q4 = *(const float4*)(Qg + (size_t)r * DM + c);
        Qs[r * AT_STR + c + 0] = q4.x;
        Qs[r * AT_STR + c + 1] = q4.y;
        Qs[r * AT_STR + c + 2] = q4.z;
        Qs[r * AT_STR + c + 3] = q4.w;
    }

    float mrow[8], lrow[8], o[8][4];
#pragma unroll
    for (int i = 0; i < 8; i++) {
        mrow[i] = -1e30f; lrow[i] = 0.f;
#pragma unroll
        for (int j = 0; j < 4; j++) o[i][j] = 0.f;
    }

    for (int s0 = 0; s0 < SK; s0 += AT_BN) {
        __syncthreads();   // previous iteration's Ps/Vs reads done
        // load K,V tiles 64x64
#pragma unroll
        for (int it = 0; it < 4; it++) {
            int v = tid + 256 * it;    // 0..1023
            int r = v >> 4;            // 0..63
            int c = (v & 15) * 4;
            float4 k4 = *(const float4*)(Kg + (size_t)(s0 + r) * DM + c);
            Ks[r * AT_STR + c + 0] = k4.x;
            Ks[r * AT_STR + c + 1] = k4.y;
            Ks[r * AT_STR + c + 2] = k4.z;
            Ks[r * AT_STR + c + 3] = k4.w;
            float4 v4 = *(const float4*)(Vg + (size_t)(s0 + r) * DM + c);
            Vs[r * AT_STR + c + 0] = v4.x;
            Vs[r * AT_STR + c + 1] = v4.y;
            Vs[r * AT_STR + c + 2] = v4.z;
            Vs[r * AT_STR + c + 3] = v4.w;
        }
        __syncthreads();

        // scores: S = Q @ K^T (8x4 per thread)
        float sc[8][4];
#pragma unroll
        for (int i = 0; i < 8; i++)
#pragma unroll
            for (int j = 0; j < 4; j++) sc[i][j] = 0.f;
#pragma unroll 8
        for (int e = 0; e < DHEAD; e++) {
            float a[8], bb[4];
#pragma unroll
            for (int i = 0; i < 8; i++) a[i] = Qs[(ty * 8 + i) * AT_STR + e];
#pragma unroll
            for (int j = 0; j < 4; j++) bb[j] = Ks[(tx * 4 + j) * AT_STR + e];
#pragma unroll
            for (int i = 0; i < 8; i++)
#pragma unroll
                for (int j = 0; j < 4; j++) sc[i][j] += a[i] * bb[j];
        }

        // online softmax update per row (reduce over 16 tx lanes)
#pragma unroll
        for (int i = 0; i < 8; i++) {
            float tmax = -1e30f;
#pragma unroll
            for (int j = 0; j < 4; j++) {
                sc[i][j] *= scale;
                tmax = fmaxf(tmax, sc[i][j]);
            }
#pragma unroll
            for (int off = 8; off >= 1; off >>= 1)
                tmax = fmaxf(tmax, __shfl_xor_sync(0xffffffffu, tmax, off));
            float mnew = fmaxf(mrow[i], tmax);
            float alpha = __expf(mrow[i] - mnew);
            float ssum = 0.f;
#pragma unroll
            for (int j = 0; j < 4; j++) {
                sc[i][j] = __expf(sc[i][j] - mnew);
                ssum += sc[i][j];
            }
#pragma unroll
            for (int off = 8; off >= 1; off >>= 1)
                ssum += __shfl_xor_sync(0xffffffffu, ssum, off);
            lrow[i] = lrow[i] * alpha + ssum;
            mrow[i] = mnew;
#pragma unroll
            for (int j = 0; j < 4; j++) o[i][j] *= alpha;
        }

        // stage P in smem for the PV GEMM
#pragma unroll
        for (int i = 0; i < 8; i++)
#pragma unroll
            for (int j = 0; j < 4; j++)
                Ps[(ty * 8 + i) * AT_STR + tx * 4 + j] = sc[i][j];
        __syncthreads();

        // O += P @ V
#pragma unroll 8
        for (int s = 0; s < AT_BN; s++) {
            float a[8], bb[4];
#pragma unroll
            for (int i = 0; i < 8; i++) a[i] = Ps[(ty * 8 + i) * AT_STR + s];
#pragma unroll
            for (int j = 0; j < 4; j++) bb[j] = Vs[s * AT_STR + tx * 4 + j];
#pragma unroll
            for (int i = 0; i < 8; i++)
#pragma unroll
                for (int j = 0; j < 4; j++) o[i][j] += a[i] * bb[j];
        }
    }

    // normalize + store
    float* Og = Aout + ((size_t)(b * LQ + l0)) * DM + h * DHEAD;
#pragma unroll
    for (int i = 0; i < 8; i++) {
        float inv = 1.f / lrow[i];
        float4 w;
        w.x = o[i][0] * inv; w.y = o[i][1] * inv;
        w.z = o[i][2] * inv; w.w = o[i][3] * inv;
        *(float4*)(Og + (size_t)(ty * 8 + i) * DM + tx * 4) = w;
    }
}

// ---------------------------------------------------------------------------
// kernel_launch
// ---------------------------------------------------------------------------
extern "C" void kernel_launch(void* const* d_in, const int* in_sizes, int n_in,
                              void* d_out, int out_size)
{
    const float* tgt = (const float*)d_in[0];   // [4,2048,1024]
    const float* src = (const float*)d_in[1];   // [4,1024,4096]
    const float* val = (const float*)d_in[2];   // [4,1024,4096]
    const float* Wq  = (const float*)d_in[3];
    const float* bq  = (const float*)d_in[4];
    const float* Wk  = (const float*)d_in[5];
    const float* bk  = (const float*)d_in[6];
    const float* Wv  = (const float*)d_in[7];
    const float* bv  = (const float*)d_in[8];
    const float* Wo  = (const float*)d_in[9];
    const float* bo  = (const float*)d_in[10];
    float* out = (float*)d_out;                 // [4,2048,1024]

    float *pQ, *pK, *pV, *pA;
    cudaGetSymbolAddress((void**)&pQ, g_Q);
    cudaGetSymbolAddress((void**)&pK, g_K);
    cudaGetSymbolAddress((void**)&pV, g_V);
    cudaGetSymbolAddress((void**)&pA, g_A);

    const int attn_smem = (AT_BM + AT_BN + AT_BN + AT_BM) * AT_STR * (int)sizeof(float);
    cudaFuncSetAttribute(attn_kernel, cudaFuncAttributeMaxDynamicSharedMemorySize, attn_smem);

    // Q = target @ Wq + bq   : [8192,1024] x [1024,1024]
    sgemm_bias<<<dim3(DM / GBN, (BSZ * LQ) / GBM), 256>>>(tgt, Wq, bq, pQ, BSZ * LQ, DM, DM);
    // K = source @ Wk + bk   : [4096,4096] x [4096,1024]
    sgemm_bias<<<dim3(DM / GBN, (BSZ * SK) / GBM), 256>>>(src, Wk, bk, pK, BSZ * SK, DM, DL);
    // V = value @ Wv + bv
    sgemm_bias<<<dim3(DM / GBN, (BSZ * SK) / GBM), 256>>>(val, Wv, bv, pV, BSZ * SK, DM, DL);
    // attention
    attn_kernel<<<dim3(LQ / AT_BM, NH, BSZ), 256, attn_smem>>>(pQ, pK, pV, pA);
    // out = A @ Wo + bo
    sgemm_bias<<<dim3(DM / GBN, (BSZ * LQ) / GBM), 256>>>(pA, Wo, bo, out, BSZ * LQ, DM, DM);
}

// round 8
// speedup vs baseline: 1.6738x; 1.6738x over previous
#include <cuda_runtime.h>
#include <math.h>
#include <cstdint>

// ---------------------------------------------------------------------------
// Problem dims
// ---------------------------------------------------------------------------
#define BSZ 4
#define LQ  2048
#define SK  1024
#define DM  1024
#define DL  4096
#define NH  16
#define DHEAD 64

// ---------------------------------------------------------------------------
// Scratch
// ---------------------------------------------------------------------------
__device__ float g_Q[(size_t)BSZ * LQ * DM];
__device__ float g_K[(size_t)BSZ * SK * DM];
__device__ float g_V[(size_t)BSZ * SK * DM];
__device__ float g_A[(size_t)BSZ * LQ * DM];

// ---------------------------------------------------------------------------
// helpers
// ---------------------------------------------------------------------------
__device__ __forceinline__ uint32_t f2tf32(float x) {
    uint32_t r;
    asm("cvt.rna.tf32.f32 %0, %1;" : "=r"(r) : "f"(x));
    return r;
}

// D += A(16x8,row) * B(8x8,col)  tf32, f32 accum  (base ISA sm_80+)
__device__ __forceinline__ void mma_tf32(float* c,
                                         uint32_t a0, uint32_t a1, uint32_t a2, uint32_t a3,
                                         uint32_t b0, uint32_t b1) {
    asm volatile(
        "mma.sync.aligned.m16n8k8.row.col.f32.tf32.tf32.f32 "
        "{%0,%1,%2,%3}, {%4,%5,%6,%7}, {%8,%9}, {%0,%1,%2,%3};"
        : "+f"(c[0]), "+f"(c[1]), "+f"(c[2]), "+f"(c[3])
        : "r"(a0), "r"(a1), "r"(a2), "r"(a3), "r"(b0), "r"(b1));
}

// ---------------------------------------------------------------------------
// tf32 mma.sync GEMM + bias: C[M,N] = A[M,K] @ W[K,N] + bias
//   BM=128, BN=128, BK=16. 256 threads = 8 warps (2 M x 4 N), warp tile 64x32.
//   STATIC shared memory (32 KB), flat code: no extern smem, no lambda,
//   no dynamic-indexed pointer arrays.
//
//   Reg-plane-major smem:
//     A: sAbuf[buf][(F*4 + reg)*32 + lane]   F = ks*8 + fm,  ks in {0,1}
//     B: sBbuf[buf][(G*2 + reg)*32 + lane]   G = ks*16 + fn
//   -> every fragment-register fetch = 32 consecutive u32 (conflict-free LDS).
// ---------------------------------------------------------------------------
#define BM 128
#define BN 128
#define BKT 16

__shared__ uint32_t sAbuf[2][2048];   // 128 rows x 16 k  (8 KB each)
__shared__ uint32_t sBbuf[2][2048];   // 16 k x 128 n

__global__ __launch_bounds__(256) void gemm_mma(
    const float* __restrict__ A, const float* __restrict__ W,
    const float* __restrict__ bias, float* __restrict__ C,
    int M, int N, int K)
{
    const int tid = threadIdx.x;
    const int lane = tid & 31;
    const int warp = tid >> 5;
    const int wm = warp & 1;    // 0..1 -> 64 rows each
    const int wn = warp >> 1;   // 0..3 -> 32 cols each
    const int m0 = blockIdx.y * BM;
    const int n0 = blockIdx.x * BN;

    float acc[4][4][4];
#pragma unroll
    for (int i = 0; i < 4; i++)
#pragma unroll
        for (int j = 0; j < 4; j++)
#pragma unroll
            for (int r = 0; r < 4; r++) acc[i][j][r] = 0.f;

    const int T = K / BKT;

    // ---------------- prologue: load tile 0 into buffer 0 ----------------
    {
        const int k0 = 0;
#pragma unroll
        for (int i = 0; i < 2; i++) {           // A: 512 float4 slots
            int v = tid + 256 * i;              // 0..511
            int r = v >> 2;                     // row 0..127
            int c4 = v & 3;                     // k/4 in 16
            float4 q = *(const float4*)(A + (size_t)(m0 + r) * K + k0 + c4 * 4);
            int F = (c4 >> 1) * 8 + (r >> 4);
            int reg = (((r & 15) >= 8) ? 1 : 0) + ((c4 & 1) ? 2 : 0);
            uint32_t* p = &sAbuf[0][(F * 4 + reg) * 32 + (r & 7) * 4];
            p[0] = f2tf32(q.x); p[1] = f2tf32(q.y);
            p[2] = f2tf32(q.z); p[3] = f2tf32(q.w);
        }
#pragma unroll
        for (int i = 0; i < 2; i++) {           // B: 512 (n,k4) slots
            int v = tid + 256 * i;              // 0..511
            int n = v & 127;
            int k4 = v >> 7;                    // 0..3
            const float* wp = W + (size_t)(k0 + k4 * 4) * N + n0 + n;
            int G = (k4 >> 1) * 16 + (n >> 3);
            int reg = k4 & 1;
            uint32_t* p = &sBbuf[0][(G * 2 + reg) * 32 + (n & 7) * 4];
            p[0] = f2tf32(wp[0]);
            p[1] = f2tf32(wp[(size_t)N]);
            p[2] = f2tf32(wp[(size_t)2 * N]);
            p[3] = f2tf32(wp[(size_t)3 * N]);
        }
    }
    __syncthreads();

    // ---------------- main loop ----------------
    for (int t = 0; t < T; t++) {
        const int cur = t & 1;
        const int nxt = cur ^ 1;

        if (t + 1 < T) {
            const int k0 = (t + 1) * BKT;
#pragma unroll
            for (int i = 0; i < 2; i++) {
                int v = tid + 256 * i;
                int r = v >> 2;
                int c4 = v & 3;
                float4 q = *(const float4*)(A + (size_t)(m0 + r) * K + k0 + c4 * 4);
                int F = (c4 >> 1) * 8 + (r >> 4);
                int reg = (((r & 15) >= 8) ? 1 : 0) + ((c4 & 1) ? 2 : 0);
                uint32_t* p = &sAbuf[nxt][(F * 4 + reg) * 32 + (r & 7) * 4];
                p[0] = f2tf32(q.x); p[1] = f2tf32(q.y);
                p[2] = f2tf32(q.z); p[3] = f2tf32(q.w);
            }
#pragma unroll
            for (int i = 0; i < 2; i++) {
                int v = tid + 256 * i;
                int n = v & 127;
                int k4 = v >> 7;
                const float* wp = W + (size_t)(k0 + k4 * 4) * N + n0 + n;
                int G = (k4 >> 1) * 16 + (n >> 3);
                int reg = k4 & 1;
                uint32_t* p = &sBbuf[nxt][(G * 2 + reg) * 32 + (n & 7) * 4];
                p[0] = f2tf32(wp[0]);
                p[1] = f2tf32(wp[(size_t)N]);
                p[2] = f2tf32(wp[(size_t)2 * N]);
                p[3] = f2tf32(wp[(size_t)3 * N]);
            }
        }

        // consume buffer cur
#pragma unroll
        for (int ks = 0; ks < 2; ks++) {
            uint32_t a0[4], a1[4], a2[4], a3[4], b0[4], b1[4];
#pragma unroll
            for (int i = 0; i < 4; i++) {
                int F = ks * 8 + wm * 4 + i;
                const uint32_t* p = &sAbuf[cur][F * 128 + lane];
                a0[i] = p[0];  a1[i] = p[32];
                a2[i] = p[64]; a3[i] = p[96];
            }
#pragma unroll
            for (int j = 0; j < 4; j++) {
                int G = ks * 16 + wn * 4 + j;
                const uint32_t* p = &sBbuf[cur][G * 64 + lane];
                b0[j] = p[0]; b1[j] = p[32];
            }
#pragma unroll
            for (int i = 0; i < 4; i++)
#pragma unroll
                for (int j = 0; j < 4; j++)
                    mma_tf32(acc[i][j], a0[i], a1[i], a2[i], a3[i], b0[j], b1[j]);
        }
        __syncthreads();
    }

    // ---------------- epilogue: bias + store (scalar STG) ----------------
    const int row = lane >> 2;
    const int qc  = (lane & 3) * 2;
    const int mb_ = m0 + wm * 64;
    const int nb_ = n0 + wn * 32;
#pragma unroll
    for (int j = 0; j < 4; j++) {
        int n_ = nb_ + j * 8 + qc;
        float b0v = bias[n_], b1v = bias[n_ + 1];
#pragma unroll
        for (int i = 0; i < 4; i++) {
            int m_ = mb_ + i * 16 + row;
            float* c0 = C + (size_t)m_ * N + n_;
            float* c1 = C + (size_t)(m_ + 8) * N + n_;
            c0[0] = acc[i][j][0] + b0v;
            c0[1] = acc[i][j][1] + b1v;
            c1[0] = acc[i][j][2] + b0v;
            c1[1] = acc[i][j][3] + b1v;
        }
    }
}

// ---------------------------------------------------------------------------
// Flash-style attention (byte-identical to the round-1 PASSING version)
// ---------------------------------------------------------------------------
#define AT_BM 128
#define AT_BN 64
#define AT_STR 65

__global__ __launch_bounds__(256, 2) void attn_kernel(
    const float* __restrict__ Q, const float* __restrict__ K,
    const float* __restrict__ V, float* __restrict__ Aout)
{
    extern __shared__ float smf[];
    float* Qs = smf;
    float* Ks = Qs + AT_BM * AT_STR;
    float* Vs = Ks + AT_BN * AT_STR;
    float* Ps = Vs + AT_BN * AT_STR;

    const int tid = threadIdx.x;
    const int tx = tid & 15;
    const int ty = tid >> 4;
    const int mt = blockIdx.x;
    const int h  = blockIdx.y;
    const int b  = blockIdx.z;
    const int l0 = mt * AT_BM;
    const float scale = 0.125f;

    const float* Qg = Q + ((size_t)(b * LQ + l0)) * DM + h * DHEAD;
    const float* Kg = K + ((size_t)(b * SK)) * DM + h * DHEAD;
    const float* Vg = V + ((size_t)(b * SK)) * DM + h * DHEAD;

#pragma unroll
    for (int it = 0; it < 8; it++) {
        int v = tid + 256 * it;
        int r = v >> 4;
        int c = (v & 15) * 4;
        float4 q4 = *(const float4*)(Qg + (size_t)r * DM + c);
        Qs[r * AT_STR + c + 0] = q4.x;
        Qs[r * AT_STR + c + 1] = q4.y;
        Qs[r * AT_STR + c + 2] = q4.z;
        Qs[r * AT_STR + c + 3] = q4.w;
    }

    float mrow[8], lrow[8], o[8][4];
#pragma unroll
    for (int i = 0; i < 8; i++) {
        mrow[i] = -1e30f; lrow[i] = 0.f;
#pragma unroll
        for (int j = 0; j < 4; j++) o[i][j] = 0.f;
    }

    for (int s0 = 0; s0 < SK; s0 += AT_BN) {
        __syncthreads();
#pragma unroll
        for (int it = 0; it < 4; it++) {
            int v = tid + 256 * it;
            int r = v >> 4;
            int c = (v & 15) * 4;
            float4 k4 = *(const float4*)(Kg + (size_t)(s0 + r) * DM + c);
            Ks[r * AT_STR + c + 0] = k4.x;
            Ks[r * AT_STR + c + 1] = k4.y;
            Ks[r * AT_STR + c + 2] = k4.z;
            Ks[r * AT_STR + c + 3] = k4.w;
            float4 v4 = *(const float4*)(Vg + (size_t)(s0 + r) * DM + c);
            Vs[r * AT_STR + c + 0] = v4.x;
            Vs[r * AT_STR + c + 1] = v4.y;
            Vs[r * AT_STR + c + 2] = v4.z;
            Vs[r * AT_STR + c + 3] = v4.w;
        }
        __syncthreads();

        float sc[8][4];
#pragma unroll
        for (int i = 0; i < 8; i++)
#pragma unroll
            for (int j = 0; j < 4; j++) sc[i][j] = 0.f;
#pragma unroll 8
        for (int e = 0; e < DHEAD; e++) {
            float a[8], bb[4];
#pragma unroll
            for (int i = 0; i < 8; i++) a[i] = Qs[(ty * 8 + i) * AT_STR + e];
#pragma unroll
            for (int j = 0; j < 4; j++) bb[j] = Ks[(tx * 4 + j) * AT_STR + e];
#pragma unroll
            for (int i = 0; i < 8; i++)
#pragma unroll
                for (int j = 0; j < 4; j++) sc[i][j] += a[i] * bb[j];
        }

#pragma unroll
        for (int i = 0; i < 8; i++) {
            float tmax = -1e30f;
#pragma unroll
            for (int j = 0; j < 4; j++) {
                sc[i][j] *= scale;
                tmax = fmaxf(tmax, sc[i][j]);
            }
#pragma unroll
            for (int off = 8; off >= 1; off >>= 1)
                tmax = fmaxf(tmax, __shfl_xor_sync(0xffffffffu, tmax, off));
            float mnew = fmaxf(mrow[i], tmax);
            float alpha = __expf(mrow[i] - mnew);
            float ssum = 0.f;
#pragma unroll
            for (int j = 0; j < 4; j++) {
                sc[i][j] = __expf(sc[i][j] - mnew);
                ssum += sc[i][j];
            }
#pragma unroll
            for (int off = 8; off >= 1; off >>= 1)
                ssum += __shfl_xor_sync(0xffffffffu, ssum, off);
            lrow[i] = lrow[i] * alpha + ssum;
            mrow[i] = mnew;
#pragma unroll
            for (int j = 0; j < 4; j++) o[i][j] *= alpha;
        }

#pragma unroll
        for (int i = 0; i < 8; i++)
#pragma unroll
            for (int j = 0; j < 4; j++)
                Ps[(ty * 8 + i) * AT_STR + tx * 4 + j] = sc[i][j];
        __syncthreads();

#pragma unroll 8
        for (int s = 0; s < AT_BN; s++) {
            float a[8], bb[4];
#pragma unroll
            for (int i = 0; i < 8; i++) a[i] = Ps[(ty * 8 + i) * AT_STR + s];
#pragma unroll
            for (int j = 0; j < 4; j++) bb[j] = Vs[s * AT_STR + tx * 4 + j];
#pragma unroll
            for (int i = 0; i < 8; i++)
#pragma unroll
                for (int j = 0; j < 4; j++) o[i][j] += a[i] * bb[j];
        }
    }

    float* Og = Aout + ((size_t)(b * LQ + l0)) * DM + h * DHEAD;
#pragma unroll
    for (int i = 0; i < 8; i++) {
        float inv = 1.f / lrow[i];
        float4 w;
        w.x = o[i][0] * inv; w.y = o[i][1] * inv;
        w.z = o[i][2] * inv; w.w = o[i][3] * inv;
        *(float4*)(Og + (size_t)(ty * 8 + i) * DM + tx * 4) = w;
    }
}

// ---------------------------------------------------------------------------
// kernel_launch
// ---------------------------------------------------------------------------
extern "C" void kernel_launch(void* const* d_in, const int* in_sizes, int n_in,
                              void* d_out, int out_size)
{
    const float* tgt = (const float*)d_in[0];
    const float* src = (const float*)d_in[1];
    const float* val = (const float*)d_in[2];
    const float* Wq  = (const float*)d_in[3];
    const float* bq  = (const float*)d_in[4];
    const float* Wk  = (const float*)d_in[5];
    const float* bk  = (const float*)d_in[6];
    const float* Wv  = (const float*)d_in[7];
    const float* bv  = (const float*)d_in[8];
    const float* Wo  = (const float*)d_in[9];
    const float* bo  = (const float*)d_in[10];
    float* out = (float*)d_out;

    float *pQ, *pK, *pV, *pA;
    cudaGetSymbolAddress((void**)&pQ, g_Q);
    cudaGetSymbolAddress((void**)&pK, g_K);
    cudaGetSymbolAddress((void**)&pV, g_V);
    cudaGetSymbolAddress((void**)&pA, g_A);

    const int attn_smem = (AT_BM + AT_BN + AT_BN + AT_BM) * AT_STR * (int)sizeof(float);
    cudaFuncSetAttribute(attn_kernel, cudaFuncAttributeMaxDynamicSharedMemorySize, attn_smem);

    // Q = target @ Wq + bq : M=8192, N=1024, K=1024
    gemm_mma<<<dim3(DM / BN, (BSZ * LQ) / BM), 256>>>(tgt, Wq, bq, pQ, BSZ * LQ, DM, DM);
    // K = source @ Wk + bk : M=4096, N=1024, K=4096
    gemm_mma<<<dim3(DM / BN, (BSZ * SK) / BM), 256>>>(src, Wk, bk, pK, BSZ * SK, DM, DL);
    // V = value @ Wv + bv
    gemm_mma<<<dim3(DM / BN, (BSZ * SK) / BM), 256>>>(val, Wv, bv, pV, BSZ * SK, DM, DL);
    // attention
    attn_kernel<<<dim3(LQ / AT_BM, NH, BSZ), 256, attn_smem>>>(pQ, pK, pV, pA);
    // out = A @ Wo + bo
    gemm_mma<<<dim3(DM / BN, (BSZ * LQ) / BM), 256>>>(pA, Wo, bo, out, BSZ * LQ, DM, DM);
}